// round 10
// baseline (speedup 1.0000x reference)
#include <cuda_runtime.h>

// Problem constants (match reference)
#define NN 50000
#define EE 800000
#define FF 128
#define HH 128
#define CC 10
#define GG 512

// ---------------- device scratch (no allocations allowed) ----------------
__device__ int   g_ei64;            // 1 if edge_index is int64, else int32
__device__ int   g_b64;             // 1 if batch is int64
__device__ int   g_deg[NN];
__device__ int   g_rowptr[NN + 1];
__device__ int   g_cursor[NN];
__device__ int   g_csr[EE];         // src node per CSR slot (grouped by dst)
__device__ float g_dinv[NN];
__device__ float g_bufA[NN * HH];
__device__ float g_bufB[NN * HH];

// ---------------- helpers ----------------
__device__ __forceinline__ int ld_idx(const void* p, long long i, int is64) {
    if (is64) return (int)((const long long*)p)[i];
    return ((const int*)p)[i];
}

// Fused: blocks 0..95 zero deg/cursor; block 96 thread 0 detects index width.
__global__ void k_detect_zero(const int* ei, const int* batch) {
    if (blockIdx.x == 96) {
        if (threadIdx.x == 0) {
            int nz = 0;
            for (int k = 0; k < 128; k++) {
                long long j = 2LL * k * (EE / 256) + 1;   // odd word in [0, EE)
                nz += (ei[j] != 0);
            }
            g_ei64 = (nz == 0) ? 1 : 0;
            nz = 0;
            for (int k = 0; k < 128; k++) {
                long long j = 2LL * k * (NN / 256) + 1;   // odd word in [0, NN)
                nz += (batch[j] != 0);
            }
            g_b64 = (nz == 0) ? 1 : 0;
        }
        return;
    }
    int i = blockIdx.x * blockDim.x + threadIdx.x;
    int stride = 96 * blockDim.x;
    for (; i < NN; i += stride) { g_deg[i] = 0; g_cursor[i] = 0; }
}

__global__ void k_count(const void* ei) {
    int is64 = g_ei64;
    int i = blockIdx.x * blockDim.x + threadIdx.x;
    if (i < EE) {
        int d = ld_idx(ei, (long long)EE + i, is64);
        atomicAdd(&g_deg[d], 1);
    }
}

// exclusive prefix sum of g_deg -> g_rowptr, plus dinv, single 1024-thread block
__global__ void k_scan_dinv() {
    __shared__ int sums[1024];
    const int CHUNK = (NN + 1023) / 1024;             // 49
    int t = threadIdx.x;
    int lo = t * CHUNK;
    int hi = lo + CHUNK; if (hi > NN) hi = NN;
    int s = 0;
    if (lo < NN) for (int i = lo; i < hi; i++) s += g_deg[i];
    sums[t] = s;
    __syncthreads();
    for (int off = 1; off < 1024; off <<= 1) {
        int v = (t >= off) ? sums[t - off] : 0;
        __syncthreads();
        sums[t] += v;
        __syncthreads();
    }
    int run = (t == 0) ? 0 : sums[t - 1];
    if (lo < NN) {
        for (int i = lo; i < hi; i++) {
            int d = g_deg[i];
            g_rowptr[i] = run; run += d;
            g_dinv[i] = rsqrtf((float)d + 1.0f);      // +1 for self-loop
        }
        if (hi == NN) g_rowptr[NN] = run;
    }
}

__global__ void k_fill(const void* ei) {
    int is64 = g_ei64;
    int i = blockIdx.x * blockDim.x + threadIdx.x;
    if (i < EE) {
        int s = ld_idx(ei, (long long)i, is64);
        int d = ld_idx(ei, (long long)EE + i, is64);
        int pos = atomicAdd(&g_cursor[d], 1);
        g_csr[g_rowptr[d] + pos] = s;
    }
}

// ---------------- GEMM: Out[N,128] = A[N,128] @ W[128,128] ----------------
// 64x128 tile, BK=32, 256 threads, 4x8 micro-tile, packed fp32x2 FMA (FFMA2).
#define BM 64
#define BK 32
__device__ __forceinline__ void gemm_body(const float* __restrict__ A,
                                          const float* __restrict__ W,
                                          float* __restrict__ Out) {
    __shared__ float As[BK][BM + 4];   // TRANSPOSED: As[k][m]; +4 keeps rows 16B-aligned
    __shared__ float Ws[BK][HH];
    int t = threadIdx.x;
    int block_row = blockIdx.x * BM;
    int tr = t >> 4;       // 0..15 -> rows tr*4 .. tr*4+3
    int tc = t & 15;       // 0..15 -> cols tc*8 .. tc*8+7

    // acc packed: acc2[i][j2] holds (acc[i][2*j2], acc[i][2*j2+1]) as f32x2
    unsigned long long acc2[4][4];
#pragma unroll
    for (int i = 0; i < 4; i++)
#pragma unroll
        for (int j = 0; j < 4; j++) acc2[i][j] = 0ULL;

    for (int k0 = 0; k0 < FF; k0 += BK) {
        // load A tile (64 rows x 32 k): 2 float4 per thread, store transposed
#pragma unroll
        for (int i = 0; i < 2; i++) {
            int f = (t * 2 + i) * 4;
            int r = f >> 5, c = f & 31;
            int grow = block_row + r;
            float4 v = make_float4(0.f, 0.f, 0.f, 0.f);
            if (grow < NN) v = *(const float4*)&A[(long long)grow * FF + k0 + c];
            As[c + 0][r] = v.x; As[c + 1][r] = v.y;
            As[c + 2][r] = v.z; As[c + 3][r] = v.w;
        }
        // load W tile: 32x128 floats = 4 float4 per thread
#pragma unroll
        for (int i = 0; i < 4; i++) {
            int f = (t * 4 + i) * 4;
            int r = f >> 7, c = f & 127;
            *(float4*)&Ws[r][c] = *(const float4*)&W[(k0 + r) * HH + c];
        }
        __syncthreads();
#pragma unroll
        for (int kk = 0; kk < BK; kk++) {
            float4 a4 = *(const float4*)&As[kk][tr * 4];
            union { float4 f; unsigned long long u[2]; } B0, B1;
            B0.f = *(const float4*)&Ws[kk][tc * 8];
            B1.f = *(const float4*)&Ws[kk][tc * 8 + 4];
            unsigned long long b2[4] = { B0.u[0], B0.u[1], B1.u[0], B1.u[1] };
            float a_s[4] = { a4.x, a4.y, a4.z, a4.w };
#pragma unroll
            for (int i = 0; i < 4; i++) {
                unsigned long long asp;
                asm("mov.b64 %0, {%1, %1};" : "=l"(asp) : "f"(a_s[i]));
#pragma unroll
                for (int j = 0; j < 4; j++) {
                    asm("fma.rn.f32x2 %0, %1, %2, %0;"
                        : "+l"(acc2[i][j]) : "l"(asp), "l"(b2[j]));
                }
            }
        }
        __syncthreads();
    }
#pragma unroll
    for (int i = 0; i < 4; i++) {
        int grow = block_row + tr * 4 + i;
        if (grow < NN) {
            float o[8];
#pragma unroll
            for (int j = 0; j < 4; j++) {
                asm("mov.b64 {%0, %1}, %2;"
                    : "=f"(o[2 * j]), "=f"(o[2 * j + 1]) : "l"(acc2[i][j]));
            }
            *(float4*)&Out[(long long)grow * HH + tc * 8]     = make_float4(o[0], o[1], o[2], o[3]);
            *(float4*)&Out[(long long)grow * HH + tc * 8 + 4] = make_float4(o[4], o[5], o[6], o[7]);
        }
    }
}

__global__ void k_gemm_x(const float* __restrict__ x, const float* __restrict__ W) {
    gemm_body(x, W, g_bufA);               // layer 1: x @ W1 -> bufA
}
__global__ void k_gemm_h(const float* __restrict__ W) {
    gemm_body(g_bufB, W, g_bufA);          // layer 2: h1 @ W2 -> bufA
}

// -------- aggregate: out[i] = relu(dinv[i]*(sum_{s in N(i)} h[s]*dinv[s] + h[i]*dinv[i]) + b)
// one warp per node, lane owns one float4; 2-ahead index prefetch, dual accumulators
__device__ __forceinline__ void agg_body(const float* __restrict__ h,
                                         const float* __restrict__ bias,
                                         float* __restrict__ out) {
    int gw = (blockIdx.x * blockDim.x + threadIdx.x) >> 5;
    int lane = threadIdx.x & 31;
    if (gw >= NN) return;
    float di = g_dinv[gw];
    int lo = g_rowptr[gw], hi = g_rowptr[gw + 1];
    const float4* hp = (const float4*)h;
    float4 acc = hp[(long long)gw * 32 + lane];     // self term: h[i]*dinv[i]
    acc.x *= di; acc.y *= di; acc.z *= di; acc.w *= di;
    float4 acc2 = make_float4(0.f, 0.f, 0.f, 0.f);

    int e = lo;
    int s0 = (lo < hi) ? g_csr[lo] : 0;
    int s1 = (lo + 1 < hi) ? g_csr[lo + 1] : 0;
    for (; e + 1 < hi; e += 2) {
        int a0 = s0, a1 = s1;
        s0 = (e + 2 < hi) ? g_csr[e + 2] : 0;       // prefetch next pair
        s1 = (e + 3 < hi) ? g_csr[e + 3] : 0;
        float w0 = g_dinv[a0], w1 = g_dinv[a1];
        float4 v0 = hp[(long long)a0 * 32 + lane];
        float4 v1 = hp[(long long)a1 * 32 + lane];
        acc.x  = fmaf(v0.x, w0, acc.x);  acc.y  = fmaf(v0.y, w0, acc.y);
        acc.z  = fmaf(v0.z, w0, acc.z);  acc.w  = fmaf(v0.w, w0, acc.w);
        acc2.x = fmaf(v1.x, w1, acc2.x); acc2.y = fmaf(v1.y, w1, acc2.y);
        acc2.z = fmaf(v1.z, w1, acc2.z); acc2.w = fmaf(v1.w, w1, acc2.w);
    }
    if (e < hi) {
        float w = g_dinv[s0];
        float4 v = hp[(long long)s0 * 32 + lane];
        acc.x = fmaf(v.x, w, acc.x); acc.y = fmaf(v.y, w, acc.y);
        acc.z = fmaf(v.z, w, acc.z); acc.w = fmaf(v.w, w, acc.w);
    }
    acc.x += acc2.x; acc.y += acc2.y; acc.z += acc2.z; acc.w += acc2.w;

    float4 b4 = ((const float4*)bias)[lane];
    float4 o;
    o.x = fmaxf(fmaf(acc.x, di, b4.x), 0.f);
    o.y = fmaxf(fmaf(acc.y, di, b4.y), 0.f);
    o.z = fmaxf(fmaf(acc.z, di, b4.z), 0.f);
    o.w = fmaxf(fmaf(acc.w, di, b4.w), 0.f);
    ((float4*)out)[(long long)gw * 32 + lane] = o;
}

__global__ void k_agg(const float* __restrict__ bias) {
    agg_body(g_bufA, bias, g_bufB);        // both layers: bufA -> bufB
}

// -------- pool + classifier: one block per graph (batch is sorted) --------
__device__ __forceinline__ int lb_batch(const void* b, int is64, int val) {
    int lo = 0, hi = NN;
    while (lo < hi) {
        int m = (lo + hi) >> 1;
        if (ld_idx(b, m, is64) < val) lo = m + 1; else hi = m;
    }
    return lo;
}

__global__ void k_pool(const void* __restrict__ batch,
                       const float* __restrict__ Wl,
                       const float* __restrict__ bl,
                       float* __restrict__ out) {
    int g = blockIdx.x, t = threadIdx.x;   // 128 threads
    __shared__ int s_lo, s_hi;
    if (t == 0) {
        int is64 = g_b64;
        s_lo = lb_batch(batch, is64, g);
        s_hi = lb_batch(batch, is64, g + 1);
    }
    __syncthreads();
    int lo = s_lo, hi = s_hi;
    float sum = 0.f;
    for (int i = lo; i < hi; i++) sum += g_bufB[(long long)i * HH + t];
    float cnt = (hi > lo) ? (float)(hi - lo) : 1.0f;
    __shared__ float sp[HH];
    sp[t] = sum / cnt;
    __syncthreads();
    if (t < CC) {
        float a = bl[t];
#pragma unroll 8
        for (int k = 0; k < HH; k++) a = fmaf(sp[k], Wl[k * CC + t], a);
        out[g * CC + t] = a;
    }
}

// ---------------- launch ----------------
extern "C" void kernel_launch(void* const* d_in, const int* in_sizes, int n_in,
                              void* d_out, int out_size) {
    const float* x     = (const float*)d_in[0];
    const void*  ei    = d_in[1];
    const void*  batch = d_in[2];
    const float* W1    = (const float*)d_in[3];
    const float* b1    = (const float*)d_in[4];
    const float* W2    = (const float*)d_in[5];
    const float* b2    = (const float*)d_in[6];
    const float* Wl    = (const float*)d_in[7];
    const float* bl    = (const float*)d_in[8];
    float* out         = (float*)d_out;

    // Side stream + fork/join events for overlapping GEMM1 with CSR build.
    // Created once (host resource only; identical GPU work every call).
    static cudaStream_t s2 = nullptr;
    static cudaEvent_t evA = nullptr, evB = nullptr;
    if (!s2) {
        if (cudaStreamCreate(&s2) != cudaSuccess) s2 = nullptr;
        if (s2) {
            cudaEventCreateWithFlags(&evA, cudaEventDisableTiming);
            cudaEventCreateWithFlags(&evB, cudaEventDisableTiming);
        }
    }

    const int gemm_grid = (NN + BM - 1) / BM;              // 782
    const int agg_grid  = (NN * 32 + 255) / 256;           // 6250
    const int edge_grid = (EE + 255) / 256;                // 3125

    bool fork = (s2 != nullptr && evA != nullptr && evB != nullptr);
    if (fork) {
        // fork: GEMM1 (x @ W1 -> bufA) is independent of the CSR build
        cudaEventRecord(evA, 0);
        cudaStreamWaitEvent(s2, evA, 0);
        k_gemm_x<<<gemm_grid, 256, 0, s2>>>(x, W1);
        cudaEventRecord(evB, s2);
    } else {
        k_gemm_x<<<gemm_grid, 256>>>(x, W1);
    }

    // CSR build chain on the main stream
    k_detect_zero<<<97, 256>>>((const int*)ei, (const int*)batch);
    k_count<<<edge_grid, 256>>>(ei);
    k_scan_dinv<<<1, 1024>>>();
    k_fill<<<edge_grid, 256>>>(ei);

    if (fork) cudaStreamWaitEvent(0, evB, 0);              // join GEMM1

    // layer 1 aggregate
    k_agg<<<agg_grid, 256>>>(b1);                          // bufB = relu(prop(bufA)+b1)
    // layer 2
    k_gemm_h<<<gemm_grid, 256>>>(W2);                      // bufA = bufB @ W2
    k_agg<<<agg_grid, 256>>>(b2);                          // bufB = relu(prop(bufA)+b2)
    // pool + classifier
    k_pool<<<GG, HH>>>(batch, Wl, bl, out);
}